// round 2
// baseline (speedup 1.0000x reference)
#include <cuda_runtime.h>
#include <math.h>

#define NN 10000
#define EE 160000
#define DD 512
#define CC 64

// ---- scratch (device globals; no runtime alloc allowed) ----
__device__ float g_p[NN * DD];      // D^{-1/2} * (X @ W)
__device__ float g_a[NN * DD];      // aggregated layer output
__device__ int   g_cnt[NN];
__device__ int   g_fill[NN];
__device__ int   g_rowptr[NN + 1];
__device__ int   g_col[EE];
__device__ float g_dis[NN];
__device__ int   g_is64;

// ---- edge dtype probe: int64 buffers have all-odd-words == 0 ----
__global__ void detect_kernel(const int* __restrict__ ei32) {
    __shared__ int nz;
    if (threadIdx.x == 0) nz = 0;
    __syncthreads();
    for (int k = threadIdx.x; k < 4096; k += 256)
        if (ei32[2 * k + 1] != 0) atomicOr(&nz, 1);
    __syncthreads();
    if (threadIdx.x == 0) g_is64 = (nz == 0) ? 1 : 0;
}

__device__ __forceinline__ int load_idx(const void* ei, int pos) {
    if (g_is64) {
        long long v = ((const long long*)ei)[pos];
        return (int)v;
    }
    return ((const int*)ei)[pos];
}

// ---- CSR build ----
__global__ void init_kernel() {
    int i = blockIdx.x * blockDim.x + threadIdx.x;
    if (i < NN) { g_cnt[i] = 0; g_fill[i] = 0; }
}

__global__ void hist_kernel(const void* __restrict__ ei) {
    int e = blockIdx.x * blockDim.x + threadIdx.x;
    if (e >= EE) return;
    int s = load_idx(ei, e);
    int d = load_idx(ei, EE + e);
    if (s == d) return;                 // existing self-loops get weight 0
    if (d < 0 || d >= NN) return;       // safety clamp
    atomicAdd(&g_cnt[d], 1);
}

__global__ void scan_kernel() {
    __shared__ int sums[1024];
    const int ITEMS = 10;               // 1024*10 >= NN
    int t = threadIdx.x;
    int base = t * ITEMS;
    int local[ITEMS];
    int s = 0;
    #pragma unroll
    for (int i = 0; i < ITEMS; i++) {
        int idx = base + i;
        int v = (idx < NN) ? g_cnt[idx] : 0;
        local[i] = s; s += v;
    }
    sums[t] = s;
    __syncthreads();
    for (int off = 1; off < 1024; off <<= 1) {
        int v = (t >= off) ? sums[t - off] : 0;
        __syncthreads();
        sums[t] += v;
        __syncthreads();
    }
    int offset = (t > 0) ? sums[t - 1] : 0;
    #pragma unroll
    for (int i = 0; i < ITEMS; i++) {
        int idx = base + i;
        if (idx < NN) g_rowptr[idx] = offset + local[i];
    }
    if (t == 1023) g_rowptr[NN] = sums[1023];
}

__global__ void dis_kernel() {
    int i = blockIdx.x * blockDim.x + threadIdx.x;
    if (i < NN) g_dis[i] = rsqrtf((float)g_cnt[i] + 1.0f);  // +1 for added self-loop
}

__global__ void fill_kernel(const void* __restrict__ ei) {
    int e = blockIdx.x * blockDim.x + threadIdx.x;
    if (e >= EE) return;
    int s = load_idx(ei, e);
    int d = load_idx(ei, EE + e);
    if (s == d) return;
    if (s < 0 || s >= NN || d < 0 || d >= NN) return;  // safety clamp
    int pos = g_rowptr[d] + atomicAdd(&g_fill[d], 1);
    g_col[pos] = s;
}

// ---- SGEMM: C[M,N] = A[M,K] @ B[K,N]; MODE 1: C=dis[row]*acc, MODE 2: C=acc+bias[col] ----
template <int BM, int BN, int BK, int TM, int TN, int MODE>
__global__ __launch_bounds__((BM / TM) * (BN / TN))
void sgemm(int M, int N, int K,
           const float* __restrict__ A, const float* __restrict__ B,
           float* __restrict__ C,
           const float* __restrict__ scale, const float* __restrict__ bias) {
    constexpr int THREADS = (BM / TM) * (BN / TN);
    __shared__ float As[BK][BM];
    __shared__ float Bs[BK][BN];
    int tid  = threadIdx.x;
    int tcol = tid % (BN / TN);
    int trow = tid / (BN / TN);
    int rowBase = blockIdx.y * BM;
    int colBase = blockIdx.x * BN;

    float acc[TM][TN] = {};

    for (int k0 = 0; k0 < K; k0 += BK) {
        #pragma unroll
        for (int i = tid; i < BM * BK; i += THREADS) {
            int r = i / BK, c = i % BK;
            int gr = rowBase + r;
            As[c][r] = (gr < M) ? A[(size_t)gr * K + k0 + c] : 0.0f;
        }
        #pragma unroll
        for (int i = tid; i < BK * BN; i += THREADS) {
            int r = i / BN, c = i % BN;
            Bs[r][c] = B[(size_t)(k0 + r) * N + colBase + c];
        }
        __syncthreads();
        #pragma unroll
        for (int kk = 0; kk < BK; kk++) {
            float ra[TM], rb[TN];
            #pragma unroll
            for (int i = 0; i < TM; i++) ra[i] = As[kk][trow * TM + i];
            #pragma unroll
            for (int j = 0; j < TN; j++) rb[j] = Bs[kk][tcol * TN + j];
            #pragma unroll
            for (int i = 0; i < TM; i++)
                #pragma unroll
                for (int j = 0; j < TN; j++)
                    acc[i][j] += ra[i] * rb[j];
        }
        __syncthreads();
    }

    #pragma unroll
    for (int i = 0; i < TM; i++) {
        int gr = rowBase + trow * TM + i;
        if (gr >= M) continue;
        float s = (MODE == 1) ? scale[gr] : 1.0f;
        #pragma unroll
        for (int j = 0; j < TN; j++) {
            int gc = colBase + tcol * TN + j;
            float v = acc[i][j];
            if (MODE == 1) v *= s;
            if (MODE == 2) v += bias[gc];
            C[(size_t)gr * N + gc] = v;
        }
    }
}

// ---- aggregation: out[i] = dis[i]*(p[i] + sum_{in} p[src]) + b; optional ReLU ----
__global__ void agg_kernel(const float* __restrict__ p, float* __restrict__ out,
                           const float* __restrict__ bias, int relu) {
    int i = blockIdx.x;
    int t = threadIdx.x;   // 128 threads, float4 each
    const float4* prow = (const float4*)(p + (size_t)i * DD);
    float4 acc = prow[t];  // self-loop term
    int beg = g_rowptr[i], end = g_rowptr[i + 1];
    for (int e = beg; e < end; e++) {
        int s = g_col[e];
        float4 v = *(const float4*)(p + (size_t)s * DD + t * 4);
        acc.x += v.x; acc.y += v.y; acc.z += v.z; acc.w += v.w;
    }
    float d = g_dis[i];
    float4 b4 = *(const float4*)(bias + t * 4);
    float4 r;
    r.x = d * acc.x + b4.x;
    r.y = d * acc.y + b4.y;
    r.z = d * acc.z + b4.z;
    r.w = d * acc.w + b4.w;
    if (relu) {
        r.x = fmaxf(r.x, 0.0f); r.y = fmaxf(r.y, 0.0f);
        r.z = fmaxf(r.z, 0.0f); r.w = fmaxf(r.w, 0.0f);
    }
    *(float4*)(out + (size_t)i * DD + t * 4) = r;
}

// ---- log-softmax over C=64, one warp per row, 4 rows per block ----
__global__ void lsm_kernel(const float* __restrict__ logits, float* __restrict__ out) {
    int row = blockIdx.x * 4 + threadIdx.y;
    int t = threadIdx.x;
    if (row >= NN) return;
    const float* lr = logits + (size_t)row * CC;
    float a = lr[t];
    float b = lr[t + 32];
    float mx = fmaxf(a, b);
    #pragma unroll
    for (int off = 16; off > 0; off >>= 1)
        mx = fmaxf(mx, __shfl_xor_sync(0xffffffff, mx, off));
    float se = expf(a - mx) + expf(b - mx);
    #pragma unroll
    for (int off = 16; off > 0; off >>= 1)
        se += __shfl_xor_sync(0xffffffff, se, off);
    float lse = logf(se) + mx;
    float* orow = out + (size_t)row * CC;
    orow[t]      = a - lse;
    orow[t + 32] = b - lse;
}

extern "C" void kernel_launch(void* const* d_in, const int* in_sizes, int n_in,
                              void* d_out, int out_size) {
    const float* x  = (const float*)d_in[0];
    const void*  ei = d_in[1];               // int32 or int64, probed on device
    const float* W1 = (const float*)d_in[2];
    const float* b1 = (const float*)d_in[3];
    const float* W2 = (const float*)d_in[4];
    const float* b2 = (const float*)d_in[5];
    const float* Wc = (const float*)d_in[6];
    const float* bc = (const float*)d_in[7];
    float* out = (float*)d_out;

    float* pP   = nullptr;
    float* pA   = nullptr;
    float* pDis = nullptr;
    cudaGetSymbolAddress((void**)&pP, g_p);
    cudaGetSymbolAddress((void**)&pA, g_a);
    cudaGetSymbolAddress((void**)&pDis, g_dis);

    // 0) probe edge_index dtype (deterministic for fixed input)
    detect_kernel<<<1, 256>>>((const int*)ei);

    // 1) graph preprocessing: CSR by dst + degree normalization
    init_kernel<<<(NN + 255) / 256, 256>>>();
    hist_kernel<<<(EE + 255) / 256, 256>>>(ei);
    scan_kernel<<<1, 1024>>>();
    dis_kernel<<<(NN + 255) / 256, 256>>>();
    fill_kernel<<<(EE + 255) / 256, 256>>>(ei);

    dim3 gridG(DD / 128, (NN + 127) / 128);
    // 2) layer 1: p = dis * (x @ W1); a = relu(dis*(p_self + sum p) + b1)
    sgemm<128, 128, 8, 8, 8, 1><<<gridG, 256>>>(NN, DD, DD, x, W1, pP, pDis, nullptr);
    agg_kernel<<<NN, 128>>>(pP, pA, b1, 1);

    // 3) layer 2
    sgemm<128, 128, 8, 8, 8, 1><<<gridG, 256>>>(NN, DD, DD, pA, W2, pP, pDis, nullptr);
    agg_kernel<<<NN, 128>>>(pP, pA, b2, 0);

    // 4) classifier: logits = a @ Wc + bc, written straight into d_out
    dim3 gridC(CC / 64, (NN + 127) / 128);
    sgemm<128, 64, 8, 8, 4, 2><<<gridC, 256>>>(NN, CC, DD, pA, Wc, out, nullptr, bc);

    // 5) log-softmax into second half of d_out
    lsm_kernel<<<(NN + 3) / 4, dim3(32, 4)>>>(out, out + (size_t)NN * CC);
}

// round 4
// speedup vs baseline: 3.5192x; 3.5192x over previous
#include <cuda_runtime.h>
#include <cuda_bf16.h>
#include <math.h>
#include <stdint.h>

#define NN 10000
#define EE 160000
#define DD 512
#define CC 64
#define NPAD 10112   // 79 * 128

// ---- scratch (device globals; zero-init; padding rows stay zero forever) ----
__device__ __nv_bfloat16 g_xhi[NPAD * DD];
__device__ __nv_bfloat16 g_xlo[NPAD * DD];
__device__ __nv_bfloat16 g_ahi[NPAD * DD];
__device__ __nv_bfloat16 g_alo[NPAD * DD];
__device__ __nv_bfloat16 g_w1hi[DD * DD];   // W1^T split: [n][k]
__device__ __nv_bfloat16 g_w1lo[DD * DD];
__device__ __nv_bfloat16 g_w2hi[DD * DD];
__device__ __nv_bfloat16 g_w2lo[DD * DD];
__device__ __nv_bfloat16 g_wchi[CC * DD];
__device__ __nv_bfloat16 g_wclo[CC * DD];
__device__ float g_p[NN * DD];
__device__ int   g_cnt[NN];
__device__ int   g_fill[NN];
__device__ int   g_rowptr[NN + 1];
__device__ int   g_col[EE];
__device__ float g_dis[NN];
__device__ int   g_is64;

// ======================= helpers =======================
__device__ __forceinline__ uint32_t smem_u32(const void* p) {
    uint32_t a;
    asm("{ .reg .u64 t; cvta.to.shared.u64 t, %1; cvt.u32.u64 %0, t; }"
        : "=r"(a) : "l"(p));
    return a;
}

#define CP_ASYNC16(dst, src) \
    asm volatile("cp.async.ca.shared.global [%0], [%1], 16;" :: "r"(dst), "l"(src))
#define CP_COMMIT() asm volatile("cp.async.commit_group;" ::: "memory")
#define CP_WAIT(n)  asm volatile("cp.async.wait_group %0;" :: "n"(n) : "memory")

__device__ __forceinline__ void ldmx4(uint32_t* r, uint32_t addr) {
    asm volatile("ldmatrix.sync.aligned.m8n8.x4.shared.b16 {%0,%1,%2,%3}, [%4];"
                 : "=r"(r[0]), "=r"(r[1]), "=r"(r[2]), "=r"(r[3]) : "r"(addr));
}
__device__ __forceinline__ void ldmx2(uint32_t* r, uint32_t addr) {
    asm volatile("ldmatrix.sync.aligned.m8n8.x2.shared.b16 {%0,%1}, [%2];"
                 : "=r"(r[0]), "=r"(r[1]) : "r"(addr));
}
__device__ __forceinline__ void mma_bf16(float* d, const uint32_t* a, const uint32_t* b) {
    asm volatile(
        "mma.sync.aligned.m16n8k16.row.col.f32.bf16.bf16.f32 "
        "{%0,%1,%2,%3}, {%4,%5,%6,%7}, {%8,%9}, {%0,%1,%2,%3};"
        : "+f"(d[0]), "+f"(d[1]), "+f"(d[2]), "+f"(d[3])
        : "r"(a[0]), "r"(a[1]), "r"(a[2]), "r"(a[3]), "r"(b[0]), "r"(b[1]));
}

// ======================= edge dtype probe =======================
__global__ void detect_kernel(const int* __restrict__ ei32) {
    __shared__ int nz;
    if (threadIdx.x == 0) nz = 0;
    __syncthreads();
    for (int k = threadIdx.x; k < 4096; k += 256)
        if (ei32[2 * k + 1] != 0) atomicOr(&nz, 1);
    __syncthreads();
    if (threadIdx.x == 0) g_is64 = (nz == 0) ? 1 : 0;
}

__device__ __forceinline__ int load_idx(const void* ei, int pos) {
    if (g_is64) return (int)((const long long*)ei)[pos];
    return ((const int*)ei)[pos];
}

// ======================= CSR build =======================
__global__ void init_kernel() {
    int i = blockIdx.x * blockDim.x + threadIdx.x;
    if (i < NN) { g_cnt[i] = 0; g_fill[i] = 0; }
}

__global__ void hist_kernel(const void* __restrict__ ei) {
    int e = blockIdx.x * blockDim.x + threadIdx.x;
    if (e >= EE) return;
    int s = load_idx(ei, e);
    int d = load_idx(ei, EE + e);
    if (s == d) return;
    if (d < 0 || d >= NN) return;
    atomicAdd(&g_cnt[d], 1);
}

__global__ void scan_kernel() {
    __shared__ int sums[1024];
    const int ITEMS = 10;
    int t = threadIdx.x;
    int base = t * ITEMS;
    int local[ITEMS];
    int s = 0;
    #pragma unroll
    for (int i = 0; i < ITEMS; i++) {
        int idx = base + i;
        int v = (idx < NN) ? g_cnt[idx] : 0;
        local[i] = s; s += v;
    }
    sums[t] = s;
    __syncthreads();
    for (int off = 1; off < 1024; off <<= 1) {
        int v = (t >= off) ? sums[t - off] : 0;
        __syncthreads();
        sums[t] += v;
        __syncthreads();
    }
    int offset = (t > 0) ? sums[t - 1] : 0;
    #pragma unroll
    for (int i = 0; i < ITEMS; i++) {
        int idx = base + i;
        if (idx < NN) g_rowptr[idx] = offset + local[i];
    }
    if (t == 1023) g_rowptr[NN] = sums[1023];
}

__global__ void dis_kernel() {
    int i = blockIdx.x * blockDim.x + threadIdx.x;
    if (i < NN) g_dis[i] = rsqrtf((float)g_cnt[i] + 1.0f);
}

__global__ void fill_kernel(const void* __restrict__ ei) {
    int e = blockIdx.x * blockDim.x + threadIdx.x;
    if (e >= EE) return;
    int s = load_idx(ei, e);
    int d = load_idx(ei, EE + e);
    if (s == d) return;
    if (s < 0 || s >= NN || d < 0 || d >= NN) return;
    int pos = g_rowptr[d] + atomicAdd(&g_fill[d], 1);
    g_col[pos] = s;
}

// ======================= bf16 split kernels =======================
__device__ __forceinline__ void split1(float v, __nv_bfloat16& h, __nv_bfloat16& l) {
    h = __float2bfloat16(v);
    l = __float2bfloat16(v - __bfloat162float(h));
}

__global__ void split_x_kernel(const float* __restrict__ x) {
    int i = blockIdx.x * blockDim.x + threadIdx.x;
    if (i >= NN * DD) return;
    __nv_bfloat16 h, l;
    split1(x[i], h, l);
    g_xhi[i] = h;
    g_xlo[i] = l;
}

// W [DD x Ncols] row-major  ->  hi/lo transposed [Ncols x DD]
__global__ void splitw_kernel(const float* __restrict__ W,
                              __nv_bfloat16* __restrict__ hi,
                              __nv_bfloat16* __restrict__ lo, int Ncols) {
    int idx = blockIdx.x * blockDim.x + threadIdx.x;
    if (idx >= Ncols * DD) return;
    int n = idx / DD, k = idx % DD;
    __nv_bfloat16 h, l;
    split1(W[(size_t)k * Ncols + n], h, l);
    hi[idx] = h;
    lo[idx] = l;
}

// ======================= bf16-split MMA GEMM =======================
// C[128 x BN] per CTA = A[128 x 512] @ B^T, 3-term bf16 split.
// A k-major [row][k]; B k-major [n][k].  Smem rows padded to 80B (conflict-free ldmatrix).
// MODE 1: C = sc[row] * acc (ldc=DD); MODE 2: C = acc + bias[col] (ldc=CC)
template <int BN, int MODE>
__global__ __launch_bounds__(256)
void gemm_mma(const __nv_bfloat16* __restrict__ Ahi, const __nv_bfloat16* __restrict__ Alo,
              const __nv_bfloat16* __restrict__ Bhi, const __nv_bfloat16* __restrict__ Blo,
              float* __restrict__ C, const float* __restrict__ sc,
              const float* __restrict__ bias) {
    constexpr int RB = 80;                    // padded row bytes (32 bf16 + 8 pad)
    constexpr int ROWS = 256 + 2 * BN;        // Ahi,Alo,Bhi,Blo rows per stage
    constexpr int SB = ROWS * RB;             // stage bytes
    constexpr int OFF_ALO = 128 * RB;
    constexpr int OFF_BHI = 256 * RB;
    constexpr int OFF_BLO = OFF_BHI + BN * RB;
    constexpr int WN = BN / 2;                // warp col extent
    constexpr int NFRAG = WN / 8;

    extern __shared__ __align__(16) char sm[];
    const uint32_t smb = smem_u32(sm);
    const int tid = threadIdx.x;
    const int lane = tid & 31, wid = tid >> 5;
    const int wr = wid >> 1, wc = wid & 1;
    const int m0 = wr * 32, n0 = wc * WN;
    const int rowBase = blockIdx.y * 128;
    const int colBase = blockIdx.x * BN;

    // ---- async stage loader ----
    auto load_stage = [&](int k0, int stage) {
        #pragma unroll
        for (int i = tid; i < ROWS * 4; i += 256) {
            int row = i >> 2, seg = i & 3;
            const __nv_bfloat16* g;
            uint32_t soff;
            if (row < 128)            { g = Ahi + (size_t)(rowBase + row) * DD;        soff = row * RB; }
            else if (row < 256)       { g = Alo + (size_t)(rowBase + row - 128) * DD;  soff = OFF_ALO + (row - 128) * RB; }
            else if (row < 256 + BN)  { g = Bhi + (size_t)(colBase + row - 256) * DD;  soff = OFF_BHI + (row - 256) * RB; }
            else                      { g = Blo + (size_t)(colBase + row - 256 - BN) * DD; soff = OFF_BLO + (row - 256 - BN) * RB; }
            CP_ASYNC16(smb + stage * SB + soff + seg * 16, g + k0 + seg * 8);
        }
        CP_COMMIT();
    };

    float acc[2][NFRAG][4];
    #pragma unroll
    for (int i = 0; i < 2; i++)
        #pragma unroll
        for (int j = 0; j < NFRAG; j++)
            #pragma unroll
            for (int q = 0; q < 4; q++) acc[i][j][q] = 0.0f;

    load_stage(0, 0);

    const int arow = lane & 15;               // ldmatrix x4 row pattern
    const int akoff = (lane >> 4) * 8;        // and k-half
    const int brow = lane & 7;
    const int bkoff = ((lane & 15) >> 3) * 8;

    for (int kt = 0; kt < 16; kt++) {
        if (kt < 15) load_stage((kt + 1) * 32, (kt + 1) & 1);
        if (kt < 15) { CP_WAIT(1); } else { CP_WAIT(0); }
        __syncthreads();
        const uint32_t sbase = smb + (kt & 1) * SB;

        #pragma unroll
        for (int ks = 0; ks < 2; ks++) {
            const int k16 = ks * 16;
            uint32_t ahi[2][4], alo[2][4];
            #pragma unroll
            for (int i = 0; i < 2; i++) {
                uint32_t ra = sbase + (m0 + i * 16 + arow) * RB + (k16 + akoff) * 2;
                ldmx4(ahi[i], ra);
                ldmx4(alo[i], ra + OFF_ALO);
            }
            #pragma unroll
            for (int j = 0; j < NFRAG; j++) {
                uint32_t rb = sbase + OFF_BHI + (n0 + j * 8 + brow) * RB + (k16 + bkoff) * 2;
                uint32_t bhi[2], blo[2];
                ldmx2(bhi, rb);
                ldmx2(blo, rb + (OFF_BLO - OFF_BHI));
                #pragma unroll
                for (int i = 0; i < 2; i++) {
                    mma_bf16(acc[i][j], ahi[i], bhi);
                    mma_bf16(acc[i][j], ahi[i], blo);
                    mma_bf16(acc[i][j], alo[i], bhi);
                }
            }
        }
        __syncthreads();
    }

    // ---- epilogue ----
    const int ldc = (MODE == 1) ? DD : CC;
    #pragma unroll
    for (int i = 0; i < 2; i++) {
        int r0 = rowBase + m0 + i * 16 + (lane >> 2);
        #pragma unroll
        for (int h = 0; h < 2; h++) {
            int r = r0 + h * 8;
            if (r >= NN) continue;
            float s = (MODE == 1) ? sc[r] : 1.0f;
            #pragma unroll
            for (int j = 0; j < NFRAG; j++) {
                int c = colBase + n0 + j * 8 + (lane & 3) * 2;
                float v0 = acc[i][j][2 * h], v1 = acc[i][j][2 * h + 1];
                if (MODE == 1) { v0 *= s; v1 *= s; }
                else           { v0 += bias[c]; v1 += bias[c + 1]; }
                *(float2*)(C + (size_t)r * ldc + c) = make_float2(v0, v1);
            }
        }
    }
}

// ======================= aggregation (writes bf16 split) =======================
__global__ void agg_kernel(const float* __restrict__ p, const float* __restrict__ bias,
                           int relu) {
    int i = blockIdx.x;
    int t = threadIdx.x;   // 128 threads, float4 each
    const float4* prow = (const float4*)(p + (size_t)i * DD);
    float4 acc = prow[t];
    int beg = g_rowptr[i], end = g_rowptr[i + 1];
    for (int e = beg; e < end; e++) {
        const float4 v = *(const float4*)(p + (size_t)g_col[e] * DD + t * 4);
        acc.x += v.x; acc.y += v.y; acc.z += v.z; acc.w += v.w;
    }
    float d = g_dis[i];
    float4 b4 = ((const float4*)bias)[t];
    float4 r;
    r.x = fmaf(d, acc.x, b4.x);
    r.y = fmaf(d, acc.y, b4.y);
    r.z = fmaf(d, acc.z, b4.z);
    r.w = fmaf(d, acc.w, b4.w);
    if (relu) {
        r.x = fmaxf(r.x, 0.0f); r.y = fmaxf(r.y, 0.0f);
        r.z = fmaxf(r.z, 0.0f); r.w = fmaxf(r.w, 0.0f);
    }
    __nv_bfloat16 h[4], l[4];
    split1(r.x, h[0], l[0]); split1(r.y, h[1], l[1]);
    split1(r.z, h[2], l[2]); split1(r.w, h[3], l[3]);
    size_t o = (size_t)i * DD + t * 4;
    *(uint2*)(g_ahi + o) = *(const uint2*)h;
    *(uint2*)(g_alo + o) = *(const uint2*)l;
}

// ======================= log-softmax =======================
__global__ void lsm_kernel(const float* __restrict__ logits, float* __restrict__ out) {
    int row = blockIdx.x * 4 + threadIdx.y;
    int t = threadIdx.x;
    if (row >= NN) return;
    const float* lr = logits + (size_t)row * CC;
    float a = lr[t];
    float b = lr[t + 32];
    float mx = fmaxf(a, b);
    #pragma unroll
    for (int off = 16; off > 0; off >>= 1)
        mx = fmaxf(mx, __shfl_xor_sync(0xffffffff, mx, off));
    float se = expf(a - mx) + expf(b - mx);
    #pragma unroll
    for (int off = 16; off > 0; off >>= 1)
        se += __shfl_xor_sync(0xffffffff, se, off);
    float lse = logf(se) + mx;
    float* orow = out + (size_t)row * CC;
    orow[t]      = a - lse;
    orow[t + 32] = b - lse;
}

// ======================= launch =======================
extern "C" void kernel_launch(void* const* d_in, const int* in_sizes, int n_in,
                              void* d_out, int out_size) {
    const float* x  = (const float*)d_in[0];
    const void*  ei = d_in[1];
    const float* W1 = (const float*)d_in[2];
    const float* b1 = (const float*)d_in[3];
    const float* W2 = (const float*)d_in[4];
    const float* b2 = (const float*)d_in[5];
    const float* Wc = (const float*)d_in[6];
    const float* bc = (const float*)d_in[7];
    float* out = (float*)d_out;

    __nv_bfloat16 *pxhi, *pxlo, *pahi, *palo;
    __nv_bfloat16 *pw1hi, *pw1lo, *pw2hi, *pw2lo, *pwchi, *pwclo;
    float *pP, *pDis;
    cudaGetSymbolAddress((void**)&pxhi, g_xhi);
    cudaGetSymbolAddress((void**)&pxlo, g_xlo);
    cudaGetSymbolAddress((void**)&pahi, g_ahi);
    cudaGetSymbolAddress((void**)&palo, g_alo);
    cudaGetSymbolAddress((void**)&pw1hi, g_w1hi);
    cudaGetSymbolAddress((void**)&pw1lo, g_w1lo);
    cudaGetSymbolAddress((void**)&pw2hi, g_w2hi);
    cudaGetSymbolAddress((void**)&pw2lo, g_w2lo);
    cudaGetSymbolAddress((void**)&pwchi, g_wchi);
    cudaGetSymbolAddress((void**)&pwclo, g_wclo);
    cudaGetSymbolAddress((void**)&pP, g_p);
    cudaGetSymbolAddress((void**)&pDis, g_dis);

    const int SMEM_BIG   = 2 * (256 + 256) * 80;   // 81920
    const int SMEM_SMALL = 2 * (256 + 128) * 80;   // 61440
    cudaFuncSetAttribute(gemm_mma<128, 1>, cudaFuncAttributeMaxDynamicSharedMemorySize, SMEM_BIG);
    cudaFuncSetAttribute(gemm_mma<64, 2>,  cudaFuncAttributeMaxDynamicSharedMemorySize, SMEM_SMALL);

    // 0) edge dtype probe
    detect_kernel<<<1, 256>>>((const int*)ei);

    // 1) CSR + degree normalization
    init_kernel<<<(NN + 255) / 256, 256>>>();
    hist_kernel<<<(EE + 255) / 256, 256>>>(ei);
    scan_kernel<<<1, 1024>>>();
    dis_kernel<<<(NN + 255) / 256, 256>>>();
    fill_kernel<<<(EE + 255) / 256, 256>>>(ei);

    // 2) bf16 splits of inputs / weights
    split_x_kernel<<<(NN * DD + 255) / 256, 256>>>(x);
    splitw_kernel<<<(DD * DD + 255) / 256, 256>>>(W1, pw1hi, pw1lo, DD);
    splitw_kernel<<<(DD * DD + 255) / 256, 256>>>(W2, pw2hi, pw2lo, DD);
    splitw_kernel<<<(CC * DD + 255) / 256, 256>>>(Wc, pwchi, pwclo, CC);

    // 3) layer 1: p = dis * (x @ W1)
    gemm_mma<128, 1><<<dim3(4, 79), 256, SMEM_BIG>>>(pxhi, pxlo, pw1hi, pw1lo, pP, pDis, nullptr);
    agg_kernel<<<NN, 128>>>(pP, b1, 1);

    // 4) layer 2
    gemm_mma<128, 1><<<dim3(4, 79), 256, SMEM_BIG>>>(pahi, palo, pw2hi, pw2lo, pP, pDis, nullptr);
    agg_kernel<<<NN, 128>>>(pP, b2, 0);

    // 5) classifier: logits = a2 @ Wc + bc -> d_out
    gemm_mma<64, 2><<<dim3(1, 79), 256, SMEM_SMALL>>>(pahi, palo, pwchi, pwclo, out, nullptr, bc);

    // 6) log-softmax -> second half of d_out
    lsm_kernel<<<(NN + 3) / 4, dim3(32, 4)>>>(out, out + (size_t)NN * CC);
}